// round 5
// baseline (speedup 1.0000x reference)
#include <cuda_runtime.h>
#include <cuda_bf16.h>
#include <cstdint>

#define DI __device__ __forceinline__

namespace {
constexpr int Bb = 8192, INN = 2048, HH = 2048, KG = 4096;
constexpr int BM = 64, BN = 128, BK = 64;        // bf16 elems per K-chunk
constexpr int NTH = 256;                          // 8 warps: 2 (M) x 4 (N)
// stage: Ah 8KB | Al 8KB | Wh 16KB | Wl 16KB = 48KB
constexpr int OFF_AL = 8192, OFF_WH = 16384, OFF_WL = 32768;
constexpr int STG_BYTES = 48 * 1024;
constexpr int NSTAGE = 2;
constexpr int SMEM_TOTAL = NSTAGE * STG_BYTES;    // 96KB -> 2 CTAs/SM
}

// bf16 hi/lo scratch
__device__ __align__(1024) __nv_bfloat16 g_CAhi[(size_t)Bb * KG];
__device__ __align__(1024) __nv_bfloat16 g_CAlo[(size_t)Bb * KG];
__device__ __align__(1024) __nv_bfloat16 g_Wghi[(size_t)HH * KG];
__device__ __align__(1024) __nv_bfloat16 g_Wglo[(size_t)HH * KG];
__device__ __align__(1024) __nv_bfloat16 g_Wihi[(size_t)HH * INN];
__device__ __align__(1024) __nv_bfloat16 g_Wilo[(size_t)HH * INN];

// ---------------- PTX helpers ----------------
DI uint32_t smem_u32(const void* p) {
    uint32_t a;
    asm("{ .reg .u64 t; cvta.to.shared.u64 t, %1; cvt.u32.u64 %0, t; }" : "=r"(a) : "l"(p));
    return a;
}
DI void cp16(uint32_t s, const void* g) {
    asm volatile("cp.async.cg.shared.global [%0], [%1], 16;" :: "r"(s), "l"(g) : "memory");
}
DI void cp_commit() { asm volatile("cp.async.commit_group;" ::: "memory"); }
template <int N>
DI void cp_wait() { asm volatile("cp.async.wait_group %0;" :: "n"(N) : "memory"); }

DI void ldsm_x4(uint32_t* r, uint32_t addr) {
    asm volatile("ldmatrix.sync.aligned.m8n8.x4.shared.b16 {%0,%1,%2,%3}, [%4];"
                 : "=r"(r[0]), "=r"(r[1]), "=r"(r[2]), "=r"(r[3]) : "r"(addr));
}
DI void mma_bf16(float* d, const uint32_t* a, const uint32_t* b) {
    asm volatile(
        "mma.sync.aligned.m16n8k16.row.col.f32.bf16.bf16.f32 "
        "{%0,%1,%2,%3}, {%4,%5,%6,%7}, {%8,%9}, {%0,%1,%2,%3};"
        : "+f"(d[0]), "+f"(d[1]), "+f"(d[2]), "+f"(d[3])
        : "r"(a[0]), "r"(a[1]), "r"(a[2]), "r"(a[3]), "r"(b[0]), "r"(b[1]));
}

// swizzled byte offset for (row, 16B-chunk c16) in a 128B-row tile
DI uint32_t swz(int row, int c16) {
    return (uint32_t)(row * 128 + ((c16 ^ (row & 7)) << 4));
}

// ---------------- conversion kernels ----------------
DI void hilo4(float4 v, __nv_bfloat162* h, __nv_bfloat162* l) {
    __nv_bfloat162 h0 = __floats2bfloat162_rn(v.x, v.y);
    __nv_bfloat162 h1 = __floats2bfloat162_rn(v.z, v.w);
    float r0 = v.x - __low2float(h0), r1 = v.y - __high2float(h0);
    float r2 = v.z - __low2float(h1), r3 = v.w - __high2float(h1);
    h[0] = h0; h[1] = h1;
    l[0] = __floats2bfloat162_rn(r0, r1);
    l[1] = __floats2bfloat162_rn(r2, r3);
}

__global__ __launch_bounds__(256) void convertA(
    const float4* __restrict__ in4, const float4* __restrict__ st4,
    float4* __restrict__ concat4)
{
    int idx = blockIdx.x * blockDim.x + threadIdx.x;  // Bb*512
    int row = idx >> 9, c4 = idx & 511;

    float4 vi = in4[(size_t)row * 512 + c4];
    concat4[(size_t)row * 1024 + c4] = vi;
    size_t off = (size_t)row * KG + (size_t)c4 * 4;
    hilo4(vi, (__nv_bfloat162*)(g_CAhi + off), (__nv_bfloat162*)(g_CAlo + off));

    float4 vs = st4[(size_t)row * 512 + c4];
    concat4[(size_t)row * 1024 + 512 + c4] = vs;
    off += INN;
    hilo4(vs, (__nv_bfloat162*)(g_CAhi + off), (__nv_bfloat162*)(g_CAlo + off));
}

__global__ __launch_bounds__(256) void convertW(
    const float4* __restrict__ src, __nv_bfloat16* __restrict__ hi,
    __nv_bfloat16* __restrict__ lo, int n4)
{
    int idx = blockIdx.x * blockDim.x + threadIdx.x;
    if (idx >= n4) return;
    float4 v = src[idx];
    size_t off = (size_t)idx * 4;
    hilo4(v, (__nv_bfloat162*)(hi + off), (__nv_bfloat162*)(lo + off));
}

// ---------------- GEMM via mma.sync ----------------
DI void load_stage(uint32_t st,
                   const __nv_bfloat16* __restrict__ Ahi, const __nv_bfloat16* __restrict__ Alo,
                   const __nv_bfloat16* __restrict__ Whi, const __nv_bfloat16* __restrict__ Wlo,
                   int lda, int ldw, int bm, int bn, int kc, int t)
{
    const int r0 = t >> 2, cc = t & 3;
    // A tiles: 64 rows
    {
        const char* pAh = (const char*)(Ahi + (size_t)(bm + r0) * lda + kc);
        const char* pAl = (const char*)(Alo + (size_t)(bm + r0) * lda + kc);
        #pragma unroll
        for (int i = 0; i < 2; i++) {
            const int c16 = cc + 4 * i;
            const uint32_t so = swz(r0, c16);
            cp16(st + so,          pAh + c16 * 16);
            cp16(st + OFF_AL + so, pAl + c16 * 16);
        }
    }
    // W tiles: 128 rows
    #pragma unroll
    for (int j = 0; j < 2; j++) {
        const int r = r0 + 64 * j;
        const char* pWh = (const char*)(Whi + (size_t)(bn + r) * ldw + kc);
        const char* pWl = (const char*)(Wlo + (size_t)(bn + r) * ldw + kc);
        #pragma unroll
        for (int i = 0; i < 2; i++) {
            const int c16 = cc + 4 * i;
            const uint32_t so = swz(r, c16);
            cp16(st + OFF_WH + so, pWh + c16 * 16);
            cp16(st + OFF_WL + so, pWl + c16 * 16);
        }
    }
}

template <bool GATE>
__global__ __launch_bounds__(NTH, 2)
void gemm_mma(const __nv_bfloat16* __restrict__ Ahi, const __nv_bfloat16* __restrict__ Alo,
              const __nv_bfloat16* __restrict__ Whi, const __nv_bfloat16* __restrict__ Wlo,
              int kdim,
              const float* __restrict__ state, const float* __restrict__ bias,
              const float* __restrict__ values_in,
              float* __restrict__ out0,
              float* __restrict__ gate_o, float* __restrict__ pre_h_o,
              float* __restrict__ new_h_o)
{
    extern __shared__ char smem[];
    const uint32_t sb = smem_u32(smem);
    const int t = threadIdx.x, wid = t >> 5, lane = t & 31;
    const int warp_m = wid >> 2, warp_n = wid & 3;      // 2 x 4
    const int bm = blockIdx.y * BM, bn = blockIdx.x * BN;

    float acc[2][4][4] = {};   // [mtile][ntile][frag]

    const int nch = kdim / BK;

    // prologue: stage 0
    load_stage(sb, Ahi, Alo, Whi, Wlo, KG, kdim, bm, bn, 0, t);
    cp_commit();

    // ldmatrix lane addressing
    const int a_row = warp_m * 32 + (lane & 15);        // + mt*16
    const int a_chi = lane >> 4;                        // c16 += 2s
    const int lm = lane >> 3;
    const int b_row = warp_n * 32 + (lane & 7) + ((lm >> 1) << 3);  // + np*16
    const int b_chi = lm & 1;

    for (int k = 0; k < nch; k++) {
        // issue loads for chunk k+1 into the other stage
        if (k + 1 < nch) {
            load_stage(sb + ((k + 1) & 1) * STG_BYTES, Ahi, Alo, Whi, Wlo,
                       KG, kdim, bm, bn, (k + 1) * BK, t);
            cp_commit();
            cp_wait<1>();
        } else {
            cp_wait<0>();
        }
        __syncthreads();

        const uint32_t st = sb + (k & 1) * STG_BYTES;
        #pragma unroll
        for (int s = 0; s < 4; s++) {
            uint32_t ah[2][4], al[2][4];
            #pragma unroll
            for (int mt = 0; mt < 2; mt++) {
                const uint32_t off = swz(a_row + mt * 16, 2 * s + a_chi);
                ldsm_x4(ah[mt], st + off);
                ldsm_x4(al[mt], st + OFF_AL + off);
            }
            uint32_t bh[2][4], bl[2][4];
            #pragma unroll
            for (int np = 0; np < 2; np++) {
                const uint32_t off = swz(b_row + np * 16, 2 * s + b_chi);
                ldsm_x4(bh[np], st + OFF_WH + off);
                ldsm_x4(bl[np], st + OFF_WL + off);
            }
            // term-major: 8 independent MMAs between reuses of any acc
            #pragma unroll
            for (int mt = 0; mt < 2; mt++)
                #pragma unroll
                for (int nt = 0; nt < 4; nt++)
                    mma_bf16(acc[mt][nt], ah[mt], bh[nt >> 1] + (nt & 1) * 2);
            #pragma unroll
            for (int mt = 0; mt < 2; mt++)
                #pragma unroll
                for (int nt = 0; nt < 4; nt++)
                    mma_bf16(acc[mt][nt], ah[mt], bl[nt >> 1] + (nt & 1) * 2);
            #pragma unroll
            for (int mt = 0; mt < 2; mt++)
                #pragma unroll
                for (int nt = 0; nt < 4; nt++)
                    mma_bf16(acc[mt][nt], al[mt], bh[nt >> 1] + (nt & 1) * 2);
        }
        __syncthreads();
    }

    // epilogue
    const int er = bm + warp_m * 32 + (lane >> 2);
    const int ec = bn + warp_n * 32 + (lane & 3) * 2;

    #pragma unroll
    for (int mt = 0; mt < 2; mt++) {
        #pragma unroll
        for (int half = 0; half < 2; half++) {
            const size_t row = (size_t)(er + mt * 16 + half * 8) * HH;
            #pragma unroll
            for (int nt = 0; nt < 4; nt++) {
                const int n = ec + nt * 8;
                const float* a2 = &acc[mt][nt][half * 2];
                if (!GATE) {
                    float2 v = { tanhf(a2[0]), tanhf(a2[1]) };
                    *(float2*)(&out0[row + n]) = v;
                } else {
                    float2 bi = *(const float2*)(&bias[n]);
                    float2 sv = *(const float2*)(&state[row + n]);
                    float2 vv = *(const float2*)(&values_in[row + n]);
                    float2 pg = { a2[0] + bi.x, a2[1] + bi.y };
                    float2 g  = { fminf(fmaxf(pg.x, 0.f), 1.f), fminf(fmaxf(pg.y, 0.f), 1.f) };
                    float2 ph = { sv.x * (1.f - g.x) + vv.x * g.x,
                                  sv.y * (1.f - g.y) + vv.y * g.y };
                    float2 nh = { fmaxf(ph.x, 0.f), fmaxf(ph.y, 0.f) };
                    *(float2*)(&out0[row + n])    = pg;
                    *(float2*)(&gate_o[row + n])  = g;
                    *(float2*)(&pre_h_o[row + n]) = ph;
                    *(float2*)(&new_h_o[row + n]) = nh;
                }
            }
        }
    }
}

// ---------------- launch ----------------
extern "C" void kernel_launch(void* const* d_in, const int* in_sizes, int n_in,
                              void* d_out, int out_size) {
    const float* input  = (const float*)d_in[0];
    const float* state  = (const float*)d_in[1];
    const float* gate_w = (const float*)d_in[2];
    const float* gate_b = (const float*)d_in[3];
    const float* w_i    = (const float*)d_in[4];

    float* out = (float*)d_out;
    float* new_h    = out;
    float* concat   = new_h + (size_t)Bb * HH;
    float* pre_gate = concat + (size_t)Bb * KG;
    float* gate     = pre_gate + (size_t)Bb * HH;
    float* values   = gate + (size_t)Bb * HH;
    float* pre_h    = values + (size_t)Bb * HH;

    void *cahi, *calo, *wghi, *wglo, *wihi, *wilo;
    cudaGetSymbolAddress(&cahi, g_CAhi);
    cudaGetSymbolAddress(&calo, g_CAlo);
    cudaGetSymbolAddress(&wghi, g_Wghi);
    cudaGetSymbolAddress(&wglo, g_Wglo);
    cudaGetSymbolAddress(&wihi, g_Wihi);
    cudaGetSymbolAddress(&wilo, g_Wilo);

    cudaFuncSetAttribute(gemm_mma<false>, cudaFuncAttributeMaxDynamicSharedMemorySize, SMEM_TOTAL);
    cudaFuncSetAttribute(gemm_mma<true>,  cudaFuncAttributeMaxDynamicSharedMemorySize, SMEM_TOTAL);

    convertA<<<(Bb * 512) / 256, 256>>>((const float4*)input, (const float4*)state,
                                        (float4*)concat);
    convertW<<<(HH * KG / 4) / 256, 256>>>((const float4*)gate_w,
                                           (__nv_bfloat16*)wghi, (__nv_bfloat16*)wglo,
                                           HH * KG / 4);
    convertW<<<(HH * INN / 4) / 256, 256>>>((const float4*)w_i,
                                            (__nv_bfloat16*)wihi, (__nv_bfloat16*)wilo,
                                            HH * INN / 4);

    dim3 grid(HH / BN, Bb / BM);  // (16, 128)
    gemm_mma<false><<<grid, NTH, SMEM_TOTAL>>>(
        (const __nv_bfloat16*)cahi, (const __nv_bfloat16*)calo,
        (const __nv_bfloat16*)wihi, (const __nv_bfloat16*)wilo, INN,
        nullptr, nullptr, nullptr, values, nullptr, nullptr, nullptr);

    gemm_mma<true><<<grid, NTH, SMEM_TOTAL>>>(
        (const __nv_bfloat16*)cahi, (const __nv_bfloat16*)calo,
        (const __nv_bfloat16*)wghi, (const __nv_bfloat16*)wglo, KG,
        state, gate_b, values, pre_gate, gate, pre_h, new_h);
}

// round 6
// speedup vs baseline: 1.4524x; 1.4524x over previous
#include <cuda_runtime.h>
#include <cuda_fp16.h>
#include <cstdint>

#define DI __device__ __forceinline__

namespace {
constexpr int Bb = 8192, INN = 2048, HH = 2048, KG = 4096;
constexpr int BM = 128, BN = 128, BK = 64;
constexpr int NTH = 256;                          // 8 warps: 2 (M) x 4 (N)
// stage: Ah 16KB | Wh 16KB | Wl 16KB = 48KB
constexpr int OFF_WH = 16384, OFF_WL = 32768;
constexpr int STG_BYTES = 48 * 1024;
constexpr int NSTAGE = 3;
constexpr int SMEM_TOTAL = NSTAGE * STG_BYTES;    // 144KB, 1 CTA/SM

constexpr float WSCALE = 4096.0f;
constexpr float INV_WSCALE = 1.0f / 4096.0f;
}

// fp16 scratch
__device__ __align__(1024) __half g_CAh[(size_t)Bb * KG];
__device__ __align__(1024) __half g_Wgh[(size_t)HH * KG];
__device__ __align__(1024) __half g_Wgl[(size_t)HH * KG];
__device__ __align__(1024) __half g_Wih[(size_t)HH * INN];
__device__ __align__(1024) __half g_Wil[(size_t)HH * INN];

// ---------------- PTX helpers ----------------
DI uint32_t smem_u32(const void* p) {
    uint32_t a;
    asm("{ .reg .u64 t; cvta.to.shared.u64 t, %1; cvt.u32.u64 %0, t; }" : "=r"(a) : "l"(p));
    return a;
}
DI void cp16(uint32_t s, const void* g) {
    asm volatile("cp.async.cg.shared.global [%0], [%1], 16;" :: "r"(s), "l"(g) : "memory");
}
DI void cp_commit() { asm volatile("cp.async.commit_group;" ::: "memory"); }
template <int N>
DI void cp_wait() { asm volatile("cp.async.wait_group %0;" :: "n"(N) : "memory"); }

DI void ldsm_x4(uint32_t* r, uint32_t addr) {
    asm volatile("ldmatrix.sync.aligned.m8n8.x4.shared.b16 {%0,%1,%2,%3}, [%4];"
                 : "=r"(r[0]), "=r"(r[1]), "=r"(r[2]), "=r"(r[3]) : "r"(addr));
}
DI void mma_f16(float* d, const uint32_t* a, const uint32_t* b) {
    asm volatile(
        "mma.sync.aligned.m16n8k16.row.col.f32.f16.f16.f32 "
        "{%0,%1,%2,%3}, {%4,%5,%6,%7}, {%8,%9}, {%0,%1,%2,%3};"
        : "+f"(d[0]), "+f"(d[1]), "+f"(d[2]), "+f"(d[3])
        : "r"(a[0]), "r"(a[1]), "r"(a[2]), "r"(a[3]), "r"(b[0]), "r"(b[1]));
}

DI uint32_t swz(int row, int c16) {
    return (uint32_t)(row * 128 + ((c16 ^ (row & 7)) << 4));
}

// ---------------- conversion kernels ----------------
__global__ __launch_bounds__(256) void convertA(
    const float4* __restrict__ in4, const float4* __restrict__ st4,
    float4* __restrict__ concat4)
{
    int idx = blockIdx.x * blockDim.x + threadIdx.x;  // Bb*512
    int row = idx >> 9, c4 = idx & 511;

    float4 vi = in4[(size_t)row * 512 + c4];
    concat4[(size_t)row * 1024 + c4] = vi;
    size_t off = (size_t)row * KG + (size_t)c4 * 4;
    {
        __half2* h = (__half2*)(g_CAh + off);
        h[0] = __floats2half2_rn(vi.x, vi.y);
        h[1] = __floats2half2_rn(vi.z, vi.w);
    }

    float4 vs = st4[(size_t)row * 512 + c4];
    concat4[(size_t)row * 1024 + 512 + c4] = vs;
    off += INN;
    {
        __half2* h = (__half2*)(g_CAh + off);
        h[0] = __floats2half2_rn(vs.x, vs.y);
        h[1] = __floats2half2_rn(vs.z, vs.w);
    }
}

// W hi/lo with x4096 pre-scale
__global__ __launch_bounds__(256) void convertW(
    const float4* __restrict__ src, __half* __restrict__ hi,
    __half* __restrict__ lo, int n4)
{
    int idx = blockIdx.x * blockDim.x + threadIdx.x;
    if (idx >= n4) return;
    float4 v = src[idx];
    float s0 = v.x * WSCALE, s1 = v.y * WSCALE, s2 = v.z * WSCALE, s3 = v.w * WSCALE;
    __half h0 = __float2half_rn(s0), h1 = __float2half_rn(s1);
    __half h2 = __float2half_rn(s2), h3 = __float2half_rn(s3);
    float r0 = s0 - __half2float(h0), r1 = s1 - __half2float(h1);
    float r2 = s2 - __half2float(h2), r3 = s3 - __half2float(h3);
    size_t off = (size_t)idx * 4;
    __half2* ph = (__half2*)(hi + off);
    ph[0] = __halves2half2(h0, h1);
    ph[1] = __halves2half2(h2, h3);
    __half2* pl = (__half2*)(lo + off);
    pl[0] = __floats2half2_rn(r0, r1);
    pl[1] = __floats2half2_rn(r2, r3);
}

// ---------------- GEMM via mma.sync ----------------
DI void load_stage(uint32_t st,
                   const __half* __restrict__ Ah,
                   const __half* __restrict__ Wh, const __half* __restrict__ Wl,
                   int lda, int ldw, int bm, int bn, int kc, int t)
{
    const int r0 = t >> 2, cc = t & 3;
    #pragma unroll
    for (int j = 0; j < 2; j++) {
        const int r = r0 + 64 * j;
        const char* pA = (const char*)(Ah + (size_t)(bm + r) * lda + kc);
        const char* pH = (const char*)(Wh + (size_t)(bn + r) * ldw + kc);
        const char* pL = (const char*)(Wl + (size_t)(bn + r) * ldw + kc);
        #pragma unroll
        for (int i = 0; i < 2; i++) {
            const int c16 = cc + 4 * i;
            const uint32_t so = swz(r, c16);
            cp16(st + so,          pA + c16 * 16);
            cp16(st + OFF_WH + so, pH + c16 * 16);
            cp16(st + OFF_WL + so, pL + c16 * 16);
        }
    }
}

template <bool GATE>
__global__ __launch_bounds__(NTH, 1)
void gemm_mma(const __half* __restrict__ Ah,
              const __half* __restrict__ Wh, const __half* __restrict__ Wl,
              int kdim,
              const float* __restrict__ state, const float* __restrict__ bias,
              const float* __restrict__ values_in,
              float* __restrict__ out0,
              float* __restrict__ gate_o, float* __restrict__ pre_h_o,
              float* __restrict__ new_h_o)
{
    extern __shared__ char smem[];
    const uint32_t sb = smem_u32(smem);
    const int t = threadIdx.x, wid = t >> 5, lane = t & 31;
    const int warp_m = wid >> 2, warp_n = wid & 3;      // 2 x 4
    const int bm = blockIdx.y * BM, bn = blockIdx.x * BN;

    float acc[4][4][4] = {};   // [mtile][ntile][frag]

    const int nch = kdim / BK;

    load_stage(sb, Ah, Wh, Wl, KG, kdim, bm, bn, 0, t);
    cp_commit();
    load_stage(sb + STG_BYTES, Ah, Wh, Wl, KG, kdim, bm, bn, BK, t);
    cp_commit();

    const int a_row = warp_m * 64 + (lane & 15);
    const int a_chi = lane >> 4;
    const int lm = lane >> 3;
    const int b_row = warp_n * 32 + (lane & 7) + ((lm >> 1) << 3);
    const int b_chi = lm & 1;

    int s_cur = 0, s_nxt = 2;
    for (int k = 0; k < nch; k++) {
        if (k + 1 < nch) cp_wait<1>(); else cp_wait<0>();
        __syncthreads();

        if (k + 2 < nch) {
            load_stage(sb + s_nxt * STG_BYTES, Ah, Wh, Wl,
                       KG, kdim, bm, bn, (k + 2) * BK, t);
            cp_commit();
        }

        const uint32_t st = sb + s_cur * STG_BYTES;
        #pragma unroll
        for (int s = 0; s < 4; s++) {
            uint32_t af[4][4];
            #pragma unroll
            for (int mt = 0; mt < 4; mt++) {
                const uint32_t off = swz(a_row + mt * 16, 2 * s + a_chi);
                ldsm_x4(af[mt], st + off);
            }
            uint32_t bh[2][4], bl[2][4];
            #pragma unroll
            for (int np = 0; np < 2; np++) {
                const uint32_t off = swz(b_row + np * 16, 2 * s + b_chi);
                ldsm_x4(bh[np], st + OFF_WH + off);
                ldsm_x4(bl[np], st + OFF_WL + off);
            }
            // term-major: 16 independent MMAs between acc reuses
            #pragma unroll
            for (int mt = 0; mt < 4; mt++)
                #pragma unroll
                for (int nt = 0; nt < 4; nt++)
                    mma_f16(acc[mt][nt], af[mt], bh[nt >> 1] + (nt & 1) * 2);
            #pragma unroll
            for (int mt = 0; mt < 4; mt++)
                #pragma unroll
                for (int nt = 0; nt < 4; nt++)
                    mma_f16(acc[mt][nt], af[mt], bl[nt >> 1] + (nt & 1) * 2);
        }

        s_cur = (s_cur == NSTAGE - 1) ? 0 : s_cur + 1;
        s_nxt = (s_nxt == NSTAGE - 1) ? 0 : s_nxt + 1;
    }

    // epilogue (acc carries W*4096 scale)
    const int er = bm + warp_m * 64 + (lane >> 2);
    const int ec = bn + warp_n * 32 + (lane & 3) * 2;

    #pragma unroll
    for (int mt = 0; mt < 4; mt++) {
        #pragma unroll
        for (int half = 0; half < 2; half++) {
            const size_t row = (size_t)(er + mt * 16 + half * 8) * HH;
            #pragma unroll
            for (int nt = 0; nt < 4; nt++) {
                const int n = ec + nt * 8;
                const float* a2 = &acc[mt][nt][half * 2];
                if (!GATE) {
                    float2 v = { tanhf(a2[0] * INV_WSCALE), tanhf(a2[1] * INV_WSCALE) };
                    *(float2*)(&out0[row + n]) = v;
                } else {
                    float2 bi = *(const float2*)(&bias[n]);
                    float2 sv = *(const float2*)(&state[row + n]);
                    float2 vv = *(const float2*)(&values_in[row + n]);
                    float2 pg = { a2[0] * INV_WSCALE + bi.x, a2[1] * INV_WSCALE + bi.y };
                    float2 g  = { fminf(fmaxf(pg.x, 0.f), 1.f), fminf(fmaxf(pg.y, 0.f), 1.f) };
                    float2 ph = { sv.x * (1.f - g.x) + vv.x * g.x,
                                  sv.y * (1.f - g.y) + vv.y * g.y };
                    float2 nh = { fmaxf(ph.x, 0.f), fmaxf(ph.y, 0.f) };
                    *(float2*)(&out0[row + n])    = pg;
                    *(float2*)(&gate_o[row + n])  = g;
                    *(float2*)(&pre_h_o[row + n]) = ph;
                    *(float2*)(&new_h_o[row + n]) = nh;
                }
            }
        }
    }
}

// ---------------- launch ----------------
extern "C" void kernel_launch(void* const* d_in, const int* in_sizes, int n_in,
                              void* d_out, int out_size) {
    const float* input  = (const float*)d_in[0];
    const float* state  = (const float*)d_in[1];
    const float* gate_w = (const float*)d_in[2];
    const float* gate_b = (const float*)d_in[3];
    const float* w_i    = (const float*)d_in[4];

    float* out = (float*)d_out;
    float* new_h    = out;
    float* concat   = new_h + (size_t)Bb * HH;
    float* pre_gate = concat + (size_t)Bb * KG;
    float* gate     = pre_gate + (size_t)Bb * HH;
    float* values   = gate + (size_t)Bb * HH;
    float* pre_h    = values + (size_t)Bb * HH;

    void *cah, *wgh, *wgl, *wih, *wil;
    cudaGetSymbolAddress(&cah, g_CAh);
    cudaGetSymbolAddress(&wgh, g_Wgh);
    cudaGetSymbolAddress(&wgl, g_Wgl);
    cudaGetSymbolAddress(&wih, g_Wih);
    cudaGetSymbolAddress(&wil, g_Wil);

    cudaFuncSetAttribute(gemm_mma<false>, cudaFuncAttributeMaxDynamicSharedMemorySize, SMEM_TOTAL);
    cudaFuncSetAttribute(gemm_mma<true>,  cudaFuncAttributeMaxDynamicSharedMemorySize, SMEM_TOTAL);

    convertA<<<(Bb * 512) / 256, 256>>>((const float4*)input, (const float4*)state,
                                        (float4*)concat);
    convertW<<<(HH * KG / 4) / 256, 256>>>((const float4*)gate_w,
                                           (__half*)wgh, (__half*)wgl, HH * KG / 4);
    convertW<<<(HH * INN / 4) / 256, 256>>>((const float4*)w_i,
                                            (__half*)wih, (__half*)wil, HH * INN / 4);

    dim3 grid(HH / BN, Bb / BM);  // (16, 64)
    gemm_mma<false><<<grid, NTH, SMEM_TOTAL>>>(
        (const __half*)cah, (const __half*)wih, (const __half*)wil, INN,
        nullptr, nullptr, nullptr, values, nullptr, nullptr, nullptr);

    gemm_mma<true><<<grid, NTH, SMEM_TOTAL>>>(
        (const __half*)cah, (const __half*)wgh, (const __half*)wgl, KG,
        state, gate_b, values, pre_gate, gate, pre_h, new_h);
}

// round 7
// speedup vs baseline: 2.1530x; 1.4824x over previous
#include <cuda_runtime.h>
#include <cuda_fp16.h>
#include <cstdint>

#define DI __device__ __forceinline__

namespace {
constexpr int Bb = 8192, INN = 2048, HH = 2048, KG = 4096;
constexpr int BM = 128, BN = 128, BK = 64;
constexpr int NTH = 256;                          // 8 warps: 2 (M) x 4 (N)
// stage: Ah 16KB | Wh 16KB = 32KB
constexpr int OFF_W = 16384;
constexpr int STG_BYTES = 32 * 1024;
constexpr int NSTAGE = 4;
constexpr int SMEM_TOTAL = NSTAGE * STG_BYTES;    // 128KB, 1 CTA/SM

constexpr float WSCALE = 4096.0f;
constexpr float INV_WSCALE = 1.0f / 4096.0f;
}

// fp16 scratch
__device__ __align__(1024) __half g_CAh[(size_t)Bb * KG];
__device__ __align__(1024) __half g_Wgh[(size_t)HH * KG];
__device__ __align__(1024) __half g_Wih[(size_t)HH * INN];

// ---------------- PTX helpers ----------------
DI uint32_t smem_u32(const void* p) {
    uint32_t a;
    asm("{ .reg .u64 t; cvta.to.shared.u64 t, %1; cvt.u32.u64 %0, t; }" : "=r"(a) : "l"(p));
    return a;
}
DI void cp16(uint32_t s, const void* g) {
    asm volatile("cp.async.cg.shared.global [%0], [%1], 16;" :: "r"(s), "l"(g) : "memory");
}
DI void cp_commit() { asm volatile("cp.async.commit_group;" ::: "memory"); }
template <int N>
DI void cp_wait() { asm volatile("cp.async.wait_group %0;" :: "n"(N) : "memory"); }

DI void ldsm_x4(uint32_t* r, uint32_t addr) {
    asm volatile("ldmatrix.sync.aligned.m8n8.x4.shared.b16 {%0,%1,%2,%3}, [%4];"
                 : "=r"(r[0]), "=r"(r[1]), "=r"(r[2]), "=r"(r[3]) : "r"(addr));
}
DI void mma_f16(float* d, const uint32_t* a, const uint32_t* b) {
    asm volatile(
        "mma.sync.aligned.m16n8k16.row.col.f32.f16.f16.f32 "
        "{%0,%1,%2,%3}, {%4,%5,%6,%7}, {%8,%9}, {%0,%1,%2,%3};"
        : "+f"(d[0]), "+f"(d[1]), "+f"(d[2]), "+f"(d[3])
        : "r"(a[0]), "r"(a[1]), "r"(a[2]), "r"(a[3]), "r"(b[0]), "r"(b[1]));
}

DI uint32_t swz(int row, int c16) {
    return (uint32_t)(row * 128 + ((c16 ^ (row & 7)) << 4));
}

// ---------------- conversion kernels ----------------
__global__ __launch_bounds__(256) void convertA(
    const float4* __restrict__ in4, const float4* __restrict__ st4,
    float4* __restrict__ concat4)
{
    int idx = blockIdx.x * blockDim.x + threadIdx.x;  // Bb*512
    int row = idx >> 9, c4 = idx & 511;

    float4 vi = in4[(size_t)row * 512 + c4];
    concat4[(size_t)row * 1024 + c4] = vi;
    size_t off = (size_t)row * KG + (size_t)c4 * 4;
    {
        __half2* h = (__half2*)(g_CAh + off);
        h[0] = __floats2half2_rn(vi.x, vi.y);
        h[1] = __floats2half2_rn(vi.z, vi.w);
    }

    float4 vs = st4[(size_t)row * 512 + c4];
    concat4[(size_t)row * 1024 + 512 + c4] = vs;
    off += INN;
    {
        __half2* h = (__half2*)(g_CAh + off);
        h[0] = __floats2half2_rn(vs.x, vs.y);
        h[1] = __floats2half2_rn(vs.z, vs.w);
    }
}

// W fp16 with x4096 pre-scale
__global__ __launch_bounds__(256) void convertW(
    const float4* __restrict__ src, __half* __restrict__ hi, int n4)
{
    int idx = blockIdx.x * blockDim.x + threadIdx.x;
    if (idx >= n4) return;
    float4 v = src[idx];
    __half2* ph = (__half2*)(hi + (size_t)idx * 4);
    ph[0] = __floats2half2_rn(v.x * WSCALE, v.y * WSCALE);
    ph[1] = __floats2half2_rn(v.z * WSCALE, v.w * WSCALE);
}

// ---------------- GEMM via mma.sync ----------------
DI void load_stage(uint32_t st,
                   const __half* __restrict__ Ah, const __half* __restrict__ Wh,
                   int lda, int ldw, int bm, int bn, int kc, int t)
{
    const int r0 = t >> 2, cc = t & 3;
    #pragma unroll
    for (int j = 0; j < 2; j++) {
        const int r = r0 + 64 * j;
        const char* pA = (const char*)(Ah + (size_t)(bm + r) * lda + kc);
        const char* pW = (const char*)(Wh + (size_t)(bn + r) * ldw + kc);
        #pragma unroll
        for (int i = 0; i < 2; i++) {
            const int c16 = cc + 4 * i;
            const uint32_t so = swz(r, c16);
            cp16(st + so,         pA + c16 * 16);
            cp16(st + OFF_W + so, pW + c16 * 16);
        }
    }
}

template <bool GATE>
__global__ __launch_bounds__(NTH, 1)
void gemm_mma(const __half* __restrict__ Ah, const __half* __restrict__ Wh,
              int kdim,
              const float* __restrict__ state, const float* __restrict__ bias,
              const float* __restrict__ values_in,
              float* __restrict__ out0,
              float* __restrict__ gate_o, float* __restrict__ pre_h_o,
              float* __restrict__ new_h_o)
{
    extern __shared__ char smem[];
    const uint32_t sb = smem_u32(smem);
    const int t = threadIdx.x, wid = t >> 5, lane = t & 31;
    const int warp_m = wid >> 2, warp_n = wid & 3;      // 2 x 4
    const int bm = blockIdx.y * BM, bn = blockIdx.x * BN;

    float acc[4][4][4] = {};   // [mtile][ntile][frag]

    const int nch = kdim / BK;

    load_stage(sb, Ah, Wh, KG, kdim, bm, bn, 0, t);
    cp_commit();
    load_stage(sb + STG_BYTES, Ah, Wh, KG, kdim, bm, bn, BK, t);
    cp_commit();
    load_stage(sb + 2 * STG_BYTES, Ah, Wh, KG, kdim, bm, bn, 2 * BK, t);
    cp_commit();

    const int a_row = warp_m * 64 + (lane & 15);
    const int a_chi = lane >> 4;
    const int lm = lane >> 3;
    const int b_row = warp_n * 32 + (lane & 7) + ((lm >> 1) << 3);
    const int b_chi = lm & 1;

    // fragment double buffers
    uint32_t af[2][4][4], bf[2][2][4];

    for (int k = 0; k < nch; k++) {
        if (k + 2 < nch)      cp_wait<2>();
        else if (k + 1 < nch) cp_wait<1>();
        else                  cp_wait<0>();
        __syncthreads();

        if (k + 3 < nch) {
            load_stage(sb + ((k + 3) & 3) * STG_BYTES, Ah, Wh,
                       KG, kdim, bm, bn, (k + 3) * BK, t);
            cp_commit();
        }

        const uint32_t st = sb + (k & 3) * STG_BYTES;

        // prime fragments for s=0
        #pragma unroll
        for (int mt = 0; mt < 4; mt++)
            ldsm_x4(af[0][mt], st + swz(a_row + mt * 16, a_chi));
        #pragma unroll
        for (int np = 0; np < 2; np++)
            ldsm_x4(bf[0][np], st + OFF_W + swz(b_row + np * 16, b_chi));

        #pragma unroll
        for (int s = 0; s < 4; s++) {
            const int cur = s & 1, nxt = cur ^ 1;
            if (s < 3) {   // prefetch s+1 fragments, overlapping the MMAs below
                #pragma unroll
                for (int mt = 0; mt < 4; mt++)
                    ldsm_x4(af[nxt][mt], st + swz(a_row + mt * 16, 2 * (s + 1) + a_chi));
                #pragma unroll
                for (int np = 0; np < 2; np++)
                    ldsm_x4(bf[nxt][np], st + OFF_W + swz(b_row + np * 16, 2 * (s + 1) + b_chi));
            }
            #pragma unroll
            for (int mt = 0; mt < 4; mt++)
                #pragma unroll
                for (int nt = 0; nt < 4; nt++)
                    mma_f16(acc[mt][nt], af[cur][mt], bf[cur][nt >> 1] + (nt & 1) * 2);
        }
    }

    // epilogue (acc carries W*4096 scale)
    const int er = bm + warp_m * 64 + (lane >> 2);
    const int ec = bn + warp_n * 32 + (lane & 3) * 2;

    #pragma unroll
    for (int mt = 0; mt < 4; mt++) {
        #pragma unroll
        for (int half = 0; half < 2; half++) {
            const size_t row = (size_t)(er + mt * 16 + half * 8) * HH;
            #pragma unroll
            for (int nt = 0; nt < 4; nt++) {
                const int n = ec + nt * 8;
                const float* a2 = &acc[mt][nt][half * 2];
                if (!GATE) {
                    float2 v = { tanhf(a2[0] * INV_WSCALE), tanhf(a2[1] * INV_WSCALE) };
                    *(float2*)(&out0[row + n]) = v;
                } else {
                    float2 bi = *(const float2*)(&bias[n]);
                    float2 sv = *(const float2*)(&state[row + n]);
                    float2 vv = *(const float2*)(&values_in[row + n]);
                    float2 pg = { a2[0] * INV_WSCALE + bi.x, a2[1] * INV_WSCALE + bi.y };
                    float2 g  = { fminf(fmaxf(pg.x, 0.f), 1.f), fminf(fmaxf(pg.y, 0.f), 1.f) };
                    float2 ph = { sv.x * (1.f - g.x) + vv.x * g.x,
                                  sv.y * (1.f - g.y) + vv.y * g.y };
                    float2 nh = { fmaxf(ph.x, 0.f), fmaxf(ph.y, 0.f) };
                    *(float2*)(&out0[row + n])    = pg;
                    *(float2*)(&gate_o[row + n])  = g;
                    *(float2*)(&pre_h_o[row + n]) = ph;
                    *(float2*)(&new_h_o[row + n]) = nh;
                }
            }
        }
    }
}

// ---------------- launch ----------------
extern "C" void kernel_launch(void* const* d_in, const int* in_sizes, int n_in,
                              void* d_out, int out_size) {
    const float* input  = (const float*)d_in[0];
    const float* state  = (const float*)d_in[1];
    const float* gate_w = (const float*)d_in[2];
    const float* gate_b = (const float*)d_in[3];
    const float* w_i    = (const float*)d_in[4];

    float* out = (float*)d_out;
    float* new_h    = out;
    float* concat   = new_h + (size_t)Bb * HH;
    float* pre_gate = concat + (size_t)Bb * KG;
    float* gate     = pre_gate + (size_t)Bb * HH;
    float* values   = gate + (size_t)Bb * HH;
    float* pre_h    = values + (size_t)Bb * HH;

    void *cah, *wgh, *wih;
    cudaGetSymbolAddress(&cah, g_CAh);
    cudaGetSymbolAddress(&wgh, g_Wgh);
    cudaGetSymbolAddress(&wih, g_Wih);

    cudaFuncSetAttribute(gemm_mma<false>, cudaFuncAttributeMaxDynamicSharedMemorySize, SMEM_TOTAL);
    cudaFuncSetAttribute(gemm_mma<true>,  cudaFuncAttributeMaxDynamicSharedMemorySize, SMEM_TOTAL);

    convertA<<<(Bb * 512) / 256, 256>>>((const float4*)input, (const float4*)state,
                                        (float4*)concat);
    convertW<<<(HH * KG / 4) / 256, 256>>>((const float4*)gate_w, (__half*)wgh, HH * KG / 4);
    convertW<<<(HH * INN / 4) / 256, 256>>>((const float4*)w_i, (__half*)wih, HH * INN / 4);

    dim3 grid(HH / BN, Bb / BM);  // (16, 64)
    gemm_mma<false><<<grid, NTH, SMEM_TOTAL>>>(
        (const __half*)cah, (const __half*)wih, INN,
        nullptr, nullptr, nullptr, values, nullptr, nullptr, nullptr);

    gemm_mma<true><<<grid, NTH, SMEM_TOTAL>>>(
        (const __half*)cah, (const __half*)wgh, KG,
        state, gate_b, values, pre_gate, gate, pre_h, new_h);
}

// round 8
// speedup vs baseline: 2.3525x; 1.0927x over previous
#include <cuda_runtime.h>
#include <cuda_fp16.h>
#include <cstdint>

#define DI __device__ __forceinline__

namespace {
constexpr int Bb = 8192, INN = 2048, HH = 2048, KG = 4096;
constexpr int BM = 128, BN = 128, BK = 128;       // K-chunk = two 64-col panels
constexpr int NTH = 256;                          // 8 warps: 2 (M) x 4 (N)
// stage: A panel0 16KB | A panel1 16KB | W panel0 16KB | W panel1 16KB
constexpr int OFF_AP1 = 16384, OFF_W = 32768, OFF_WP1 = 49152;
constexpr int STG_BYTES = 64 * 1024;
constexpr int NSTAGE = 3;
constexpr int SMEM_TOTAL = NSTAGE * STG_BYTES;    // 192KB, 1 CTA/SM

constexpr float WSCALE = 4096.0f;
constexpr float INV_WSCALE = 1.0f / 4096.0f;
}

// fp16 scratch
__device__ __align__(1024) __half g_CAh[(size_t)Bb * KG];
__device__ __align__(1024) __half g_Wgh[(size_t)HH * KG];
__device__ __align__(1024) __half g_Wih[(size_t)HH * INN];

// ---------------- PTX helpers ----------------
DI uint32_t smem_u32(const void* p) {
    uint32_t a;
    asm("{ .reg .u64 t; cvta.to.shared.u64 t, %1; cvt.u32.u64 %0, t; }" : "=r"(a) : "l"(p));
    return a;
}
DI void cp16(uint32_t s, const void* g) {
    asm volatile("cp.async.cg.shared.global [%0], [%1], 16;" :: "r"(s), "l"(g) : "memory");
}
DI void cp_commit() { asm volatile("cp.async.commit_group;" ::: "memory"); }
template <int N>
DI void cp_wait() { asm volatile("cp.async.wait_group %0;" :: "n"(N) : "memory"); }

DI void ldsm_x4(uint32_t* r, uint32_t addr) {
    asm volatile("ldmatrix.sync.aligned.m8n8.x4.shared.b16 {%0,%1,%2,%3}, [%4];"
                 : "=r"(r[0]), "=r"(r[1]), "=r"(r[2]), "=r"(r[3]) : "r"(addr));
}
DI void mma_f16(float* d, const uint32_t* a, const uint32_t* b) {
    asm volatile(
        "mma.sync.aligned.m16n8k16.row.col.f32.f16.f16.f32 "
        "{%0,%1,%2,%3}, {%4,%5,%6,%7}, {%8,%9}, {%0,%1,%2,%3};"
        : "+f"(d[0]), "+f"(d[1]), "+f"(d[2]), "+f"(d[3])
        : "r"(a[0]), "r"(a[1]), "r"(a[2]), "r"(a[3]), "r"(b[0]), "r"(b[1]));
}

DI uint32_t swz(int row, int c16) {
    return (uint32_t)(row * 128 + ((c16 ^ (row & 7)) << 4));
}

// ---------------- conversion kernels ----------------
__global__ __launch_bounds__(256) void convertA(
    const float4* __restrict__ in4, const float4* __restrict__ st4,
    float4* __restrict__ concat4)
{
    int idx = blockIdx.x * blockDim.x + threadIdx.x;  // Bb*512
    int row = idx >> 9, c4 = idx & 511;

    float4 vi = in4[(size_t)row * 512 + c4];
    concat4[(size_t)row * 1024 + c4] = vi;
    size_t off = (size_t)row * KG + (size_t)c4 * 4;
    {
        __half2* h = (__half2*)(g_CAh + off);
        h[0] = __floats2half2_rn(vi.x, vi.y);
        h[1] = __floats2half2_rn(vi.z, vi.w);
    }

    float4 vs = st4[(size_t)row * 512 + c4];
    concat4[(size_t)row * 1024 + 512 + c4] = vs;
    off += INN;
    {
        __half2* h = (__half2*)(g_CAh + off);
        h[0] = __floats2half2_rn(vs.x, vs.y);
        h[1] = __floats2half2_rn(vs.z, vs.w);
    }
}

__global__ __launch_bounds__(256) void convertW(
    const float4* __restrict__ src, __half* __restrict__ hi, int n4)
{
    int idx = blockIdx.x * blockDim.x + threadIdx.x;
    if (idx >= n4) return;
    float4 v = src[idx];
    __half2* ph = (__half2*)(hi + (size_t)idx * 4);
    ph[0] = __floats2half2_rn(v.x * WSCALE, v.y * WSCALE);
    ph[1] = __floats2half2_rn(v.z * WSCALE, v.w * WSCALE);
}

// ---------------- GEMM via mma.sync ----------------
// loads BK=128 columns: panel0 = cols [kc, kc+64), panel1 = [kc+64, kc+128)
DI void load_stage(uint32_t st,
                   const __half* __restrict__ Ah, const __half* __restrict__ Wh,
                   int lda, int ldw, int bm, int bn, int kc, int t)
{
    const int r0 = t >> 2, cc = t & 3;
    #pragma unroll
    for (int j = 0; j < 2; j++) {
        const int r = r0 + 64 * j;
        const char* pA = (const char*)(Ah + (size_t)(bm + r) * lda + kc);
        const char* pW = (const char*)(Wh + (size_t)(bn + r) * ldw + kc);
        #pragma unroll
        for (int i = 0; i < 2; i++) {
            const int c16 = cc + 4 * i;
            const uint32_t so = swz(r, c16);
            cp16(st + so,           pA + c16 * 16);
            cp16(st + OFF_AP1 + so, pA + 128 + c16 * 16);
            cp16(st + OFF_W + so,   pW + c16 * 16);
            cp16(st + OFF_WP1 + so, pW + 128 + c16 * 16);
        }
    }
}

template <bool GATE>
__global__ __launch_bounds__(NTH, 1)
void gemm_mma(const __half* __restrict__ Ah, const __half* __restrict__ Wh,
              int kdim,
              const float* __restrict__ state, const float* __restrict__ bias,
              const float* __restrict__ values_in,
              float* __restrict__ out0,
              float* __restrict__ gate_o, float* __restrict__ pre_h_o,
              float* __restrict__ new_h_o)
{
    extern __shared__ char smem[];
    const uint32_t sb = smem_u32(smem);
    const int t = threadIdx.x, wid = t >> 5, lane = t & 31;
    const int warp_m = wid >> 2, warp_n = wid & 3;      // 2 x 4
    const int bm = blockIdx.y * BM, bn = blockIdx.x * BN;

    float acc[4][4][4] = {};   // [mtile][ntile][frag]

    const int nch = kdim / BK;

    load_stage(sb, Ah, Wh, KG, kdim, bm, bn, 0, t);
    cp_commit();
    load_stage(sb + STG_BYTES, Ah, Wh, KG, kdim, bm, bn, BK, t);
    cp_commit();

    const int a_row = warp_m * 64 + (lane & 15);
    const int a_chi = lane >> 4;
    const int lm = lane >> 3;
    const int b_row = warp_n * 32 + (lane & 7) + ((lm >> 1) << 3);
    const int b_chi = lm & 1;

    uint32_t af[2][4][4], bf[2][2][4];

    for (int k = 0; k < nch; k++) {
        if (k + 1 < nch) cp_wait<1>(); else cp_wait<0>();
        __syncthreads();

        // buffer (k+2)%3 == buffer of (k-1): safe after the barrier above
        if (k + 2 < nch) {
            load_stage(sb + ((k + 2) % NSTAGE) * STG_BYTES, Ah, Wh,
                       KG, kdim, bm, bn, (k + 2) * BK, t);
            cp_commit();
        }

        const uint32_t st = sb + (k % NSTAGE) * STG_BYTES;

        // prime fragments for s=0 (panel 0)
        #pragma unroll
        for (int mt = 0; mt < 4; mt++)
            ldsm_x4(af[0][mt], st + swz(a_row + mt * 16, a_chi));
        #pragma unroll
        for (int np = 0; np < 2; np++)
            ldsm_x4(bf[0][np], st + OFF_W + swz(b_row + np * 16, b_chi));

        #pragma unroll
        for (int s = 0; s < 8; s++) {
            const int cur = s & 1, nxt = cur ^ 1;
            if (s < 7) {   // prefetch fragments for s+1, overlapping MMAs below
                const int s1 = s + 1;
                const uint32_t ap = st + ((s1 >> 2) ? OFF_AP1 : 0);
                const uint32_t wp = st + ((s1 >> 2) ? OFF_WP1 : OFF_W);
                const int c0 = 2 * (s1 & 3);
                #pragma unroll
                for (int mt = 0; mt < 4; mt++)
                    ldsm_x4(af[nxt][mt], ap + swz(a_row + mt * 16, c0 + a_chi));
                #pragma unroll
                for (int np = 0; np < 2; np++)
                    ldsm_x4(bf[nxt][np], wp + swz(b_row + np * 16, c0 + b_chi));
            }
            #pragma unroll
            for (int mt = 0; mt < 4; mt++)
                #pragma unroll
                for (int nt = 0; nt < 4; nt++)
                    mma_f16(acc[mt][nt], af[cur][mt], bf[cur][nt >> 1] + (nt & 1) * 2);
        }
    }

    // epilogue (acc carries W*4096 scale)
    const int er = bm + warp_m * 64 + (lane >> 2);
    const int ec = bn + warp_n * 32 + (lane & 3) * 2;

    #pragma unroll
    for (int mt = 0; mt < 4; mt++) {
        #pragma unroll
        for (int half = 0; half < 2; half++) {
            const size_t row = (size_t)(er + mt * 16 + half * 8) * HH;
            #pragma unroll
            for (int nt = 0; nt < 4; nt++) {
                const int n = ec + nt * 8;
                const float* a2 = &acc[mt][nt][half * 2];
                if (!GATE) {
                    float2 v = { tanhf(a2[0] * INV_WSCALE), tanhf(a2[1] * INV_WSCALE) };
                    *(float2*)(&out0[row + n]) = v;
                } else {
                    float2 bi = *(const float2*)(&bias[n]);
                    float2 sv = *(const float2*)(&state[row + n]);
                    float2 vv = *(const float2*)(&values_in[row + n]);
                    float2 pg = { a2[0] * INV_WSCALE + bi.x, a2[1] * INV_WSCALE + bi.y };
                    float2 g  = { fminf(fmaxf(pg.x, 0.f), 1.f), fminf(fmaxf(pg.y, 0.f), 1.f) };
                    float2 ph = { sv.x * (1.f - g.x) + vv.x * g.x,
                                  sv.y * (1.f - g.y) + vv.y * g.y };
                    float2 nh = { fmaxf(ph.x, 0.f), fmaxf(ph.y, 0.f) };
                    *(float2*)(&out0[row + n])    = pg;
                    *(float2*)(&gate_o[row + n])  = g;
                    *(float2*)(&pre_h_o[row + n]) = ph;
                    *(float2*)(&new_h_o[row + n]) = nh;
                }
            }
        }
    }
}

// ---------------- launch ----------------
extern "C" void kernel_launch(void* const* d_in, const int* in_sizes, int n_in,
                              void* d_out, int out_size) {
    const float* input  = (const float*)d_in[0];
    const float* state  = (const float*)d_in[1];
    const float* gate_w = (const float*)d_in[2];
    const float* gate_b = (const float*)d_in[3];
    const float* w_i    = (const float*)d_in[4];

    float* out = (float*)d_out;
    float* new_h    = out;
    float* concat   = new_h + (size_t)Bb * HH;
    float* pre_gate = concat + (size_t)Bb * KG;
    float* gate     = pre_gate + (size_t)Bb * HH;
    float* values   = gate + (size_t)Bb * HH;
    float* pre_h    = values + (size_t)Bb * HH;

    void *cah, *wgh, *wih;
    cudaGetSymbolAddress(&cah, g_CAh);
    cudaGetSymbolAddress(&wgh, g_Wgh);
    cudaGetSymbolAddress(&wih, g_Wih);

    cudaFuncSetAttribute(gemm_mma<false>, cudaFuncAttributeMaxDynamicSharedMemorySize, SMEM_TOTAL);
    cudaFuncSetAttribute(gemm_mma<true>,  cudaFuncAttributeMaxDynamicSharedMemorySize, SMEM_TOTAL);

    convertA<<<(Bb * 512) / 256, 256>>>((const float4*)input, (const float4*)state,
                                        (float4*)concat);
    convertW<<<(HH * KG / 4) / 256, 256>>>((const float4*)gate_w, (__half*)wgh, HH * KG / 4);
    convertW<<<(HH * INN / 4) / 256, 256>>>((const float4*)w_i, (__half*)wih, HH * INN / 4);

    dim3 grid(HH / BN, Bb / BM);  // (16, 64)
    gemm_mma<false><<<grid, NTH, SMEM_TOTAL>>>(
        (const __half*)cah, (const __half*)wih, INN,
        nullptr, nullptr, nullptr, values, nullptr, nullptr, nullptr);

    gemm_mma<true><<<grid, NTH, SMEM_TOTAL>>>(
        (const __half*)cah, (const __half*)wgh, KG,
        state, gate_b, values, pre_gate, gate, pre_h, new_h);
}

// round 9
// speedup vs baseline: 2.8466x; 1.2100x over previous
#include <cuda_runtime.h>
#include <cuda_fp16.h>
#include <cstdint>

#define DI __device__ __forceinline__

namespace {
constexpr int Bb = 8192, INN = 2048, HH = 2048, KG = 4096;
constexpr int BM = 128, BN = 128, BK = 128;       // K-chunk = two 64-col panels
constexpr int NTH = 256;                          // 8 warps: 2 (M) x 4 (N)
constexpr int OFF_AP1 = 16384, OFF_W = 32768, OFF_WP1 = 49152;
constexpr int STG_BYTES = 64 * 1024;
constexpr int NSTAGE = 3;
constexpr int SMEM_TOTAL = NSTAGE * STG_BYTES;    // 192KB, 1 CTA/SM

constexpr float WSCALE = 4096.0f;
constexpr float INV_WSCALE = 1.0f / 4096.0f;
}

// fp16 scratch
__device__ __align__(1024) __half g_CAh[(size_t)Bb * KG];
__device__ __align__(1024) __half g_Wgh[(size_t)HH * KG];
__device__ __align__(1024) __half g_Wih[(size_t)HH * INN];

// ---------------- PTX helpers ----------------
DI uint32_t smem_u32(const void* p) {
    uint32_t a;
    asm("{ .reg .u64 t; cvta.to.shared.u64 t, %1; cvt.u32.u64 %0, t; }" : "=r"(a) : "l"(p));
    return a;
}
DI void cp16(uint32_t s, const void* g) {
    asm volatile("cp.async.cg.shared.global [%0], [%1], 16;" :: "r"(s), "l"(g) : "memory");
}
DI void cp_commit() { asm volatile("cp.async.commit_group;" ::: "memory"); }
template <int N>
DI void cp_wait() { asm volatile("cp.async.wait_group %0;" :: "n"(N) : "memory"); }

DI void ldsm_x4(uint32_t* r, uint32_t addr) {
    asm volatile("ldmatrix.sync.aligned.m8n8.x4.shared.b16 {%0,%1,%2,%3}, [%4];"
                 : "=r"(r[0]), "=r"(r[1]), "=r"(r[2]), "=r"(r[3]) : "r"(addr));
}
DI void mma_f16(float* d, const uint32_t* a, const uint32_t* b) {
    asm volatile(
        "mma.sync.aligned.m16n8k16.row.col.f32.f16.f16.f32 "
        "{%0,%1,%2,%3}, {%4,%5,%6,%7}, {%8,%9}, {%0,%1,%2,%3};"
        : "+f"(d[0]), "+f"(d[1]), "+f"(d[2]), "+f"(d[3])
        : "r"(a[0]), "r"(a[1]), "r"(a[2]), "r"(a[3]), "r"(b[0]), "r"(b[1]));
}

DI uint32_t swz(int row, int c16) {
    return (uint32_t)(row * 128 + ((c16 ^ (row & 7)) << 4));
}

// ---------------- conversion kernels ----------------
__global__ __launch_bounds__(256) void convertA(
    const float4* __restrict__ in4, const float4* __restrict__ st4,
    float4* __restrict__ concat4)
{
    int idx = blockIdx.x * blockDim.x + threadIdx.x;  // Bb*512
    int row = idx >> 9, c4 = idx & 511;

    float4 vi = in4[(size_t)row * 512 + c4];
    concat4[(size_t)row * 1024 + c4] = vi;
    size_t off = (size_t)row * KG + (size_t)c4 * 4;
    {
        __half2* h = (__half2*)(g_CAh + off);
        h[0] = __floats2half2_rn(vi.x, vi.y);
        h[1] = __floats2half2_rn(vi.z, vi.w);
    }

    float4 vs = st4[(size_t)row * 512 + c4];
    concat4[(size_t)row * 1024 + 512 + c4] = vs;
    off += INN;
    {
        __half2* h = (__half2*)(g_CAh + off);
        h[0] = __floats2half2_rn(vs.x, vs.y);
        h[1] = __floats2half2_rn(vs.z, vs.w);
    }
}

__global__ __launch_bounds__(256) void convertW(
    const float4* __restrict__ src, __half* __restrict__ hi, int n4)
{
    int idx = blockIdx.x * blockDim.x + threadIdx.x;
    if (idx >= n4) return;
    float4 v = src[idx];
    __half2* ph = (__half2*)(hi + (size_t)idx * 4);
    ph[0] = __floats2half2_rn(v.x * WSCALE, v.y * WSCALE);
    ph[1] = __floats2half2_rn(v.z * WSCALE, v.w * WSCALE);
}

// ---------------- GEMM via mma.sync ----------------
// bulk load (prologue only): BK=128 cols = two 64-col panels
DI void load_stage(uint32_t st,
                   const __half* __restrict__ Ah, const __half* __restrict__ Wh,
                   int lda, int ldw, int bm, int bn, int kc, int t)
{
    const int r0 = t >> 2, cc = t & 3;
    #pragma unroll
    for (int j = 0; j < 2; j++) {
        const int r = r0 + 64 * j;
        const char* pA = (const char*)(Ah + (size_t)(bm + r) * lda + kc);
        const char* pW = (const char*)(Wh + (size_t)(bn + r) * ldw + kc);
        #pragma unroll
        for (int i = 0; i < 2; i++) {
            const int c16 = cc + 4 * i;
            const uint32_t so = swz(r, c16);
            cp16(st + so,           pA + c16 * 16);
            cp16(st + OFF_AP1 + so, pA + 128 + c16 * 16);
            cp16(st + OFF_W + so,   pW + c16 * 16);
            cp16(st + OFF_WP1 + so, pW + 128 + c16 * 16);
        }
    }
}

template <bool GATE>
__global__ __launch_bounds__(NTH, 1)
void gemm_mma(const __half* __restrict__ Ah, const __half* __restrict__ Wh,
              int kdim,
              const float* __restrict__ state, const float* __restrict__ bias,
              const float* __restrict__ values_in,
              float* __restrict__ out0,
              float* __restrict__ gate_o, float* __restrict__ pre_h_o,
              float* __restrict__ new_h_o)
{
    extern __shared__ char smem[];
    const uint32_t sb = smem_u32(smem);
    const int t = threadIdx.x, wid = t >> 5, lane = t & 31;
    const int warp_m = wid >> 2, warp_n = wid & 3;      // 2 x 4
    const int bm = blockIdx.y * BM, bn = blockIdx.x * BN;
    const int r0 = t >> 2, cc = t & 3;

    float acc[4][4][4] = {};

    const int nch = kdim / BK;

    load_stage(sb, Ah, Wh, KG, kdim, bm, bn, 0, t);
    cp_commit();
    load_stage(sb + STG_BYTES, Ah, Wh, KG, kdim, bm, bn, BK, t);
    cp_commit();

    const int a_row = warp_m * 64 + (lane & 15);
    const int a_chi = lane >> 4;
    const int lm = lane >> 3;
    const int b_row = warp_n * 32 + (lane & 7) + ((lm >> 1) << 3);
    const int b_chi = lm & 1;

    uint32_t af[2][4][4], bf[2][2][4];

    // stage 0 ready (wait<1> over {0,1}); prime s0 fragments
    cp_wait<1>();
    __syncthreads();
    #pragma unroll
    for (int mt = 0; mt < 4; mt++)
        ldsm_x4(af[0][mt], sb + swz(a_row + mt * 16, a_chi));
    #pragma unroll
    for (int np = 0; np < 2; np++)
        ldsm_x4(bf[0][np], sb + OFF_W + swz(b_row + np * 16, b_chi));

    for (int k = 0; k < nch; k++) {
        const uint32_t st  = sb + (k % NSTAGE) * STG_BYTES;           // read
        const uint32_t st2 = sb + ((k + 2) % NSTAGE) * STG_BYTES;     // write
        const int kc2 = (k + 2) * BK;
        const bool do_load = (k + 2 < nch);
        const bool more    = (k + 1 < nch);
        const uint32_t stn = sb + ((k + 1) % NSTAGE) * STG_BYTES;

        #pragma unroll
        for (int s = 0; s < 8; s++) {
            const int cur = s & 1, nxt = cur ^ 1;

            // interleaved global->smem for chunk k+2 (2 cp16 per s-step)
            if (do_load) {
                const int arr = s >> 1;      // 0:Ap0 1:Ap1 2:Wp0 3:Wp1
                const int j   = s & 1;
                const int r   = r0 + 64 * j;
                const char* gp;
                uint32_t soff;
                if (arr < 2) {
                    gp = (const char*)(Ah + (size_t)(bm + r) * KG + kc2) + (arr & 1) * 128;
                    soff = (arr & 1) ? OFF_AP1 : 0u;
                } else {
                    gp = (const char*)(Wh + (size_t)(bn + r) * (size_t)kdim + kc2) + (arr & 1) * 128;
                    soff = (arr & 1) ? OFF_WP1 : OFF_W;
                }
                const uint32_t dst = st2 + soff;
                cp16(dst + swz(r, cc),     gp + cc * 16);
                cp16(dst + swz(r, cc + 4), gp + (cc + 4) * 16);
            }

            // fragment prefetch
            if (s < 7) {
                const int s1 = s + 1;
                const uint32_t ap = st + ((s1 >> 2) ? OFF_AP1 : 0);
                const uint32_t wp = st + ((s1 >> 2) ? OFF_WP1 : OFF_W);
                const int c0 = 2 * (s1 & 3);
                #pragma unroll
                for (int mt = 0; mt < 4; mt++)
                    ldsm_x4(af[nxt][mt], ap + swz(a_row + mt * 16, c0 + a_chi));
                #pragma unroll
                for (int np = 0; np < 2; np++)
                    ldsm_x4(bf[nxt][np], wp + swz(b_row + np * 16, c0 + b_chi));
            } else if (more) {
                // cross-chunk prefetch: next chunk's s0 from stage k+1
                // (safe: s==6 did wait<0> + barrier below)
                #pragma unroll
                for (int mt = 0; mt < 4; mt++)
                    ldsm_x4(af[nxt][mt], stn + swz(a_row + mt * 16, a_chi));
                #pragma unroll
                for (int np = 0; np < 2; np++)
                    ldsm_x4(bf[nxt][np], stn + OFF_W + swz(b_row + np * 16, b_chi));
            }

            #pragma unroll
            for (int mt = 0; mt < 4; mt++)
                #pragma unroll
                for (int nt = 0; nt < 4; nt++)
                    mma_f16(acc[mt][nt], af[cur][mt], bf[cur][nt >> 1] + (nt & 1) * 2);

            if (s == 6 && more) {
                // stage k+1 fully arrived; also fences stage-k reads before
                // chunk k+1's interleaved writes reuse that buffer
                cp_wait<0>();
                __syncthreads();
            }
        }
        cp_commit();   // group = stage k+2's 16 cp16 (possibly empty)
    }

    // epilogue (acc carries W*4096 scale)
    const int er = bm + warp_m * 64 + (lane >> 2);
    const int ec = bn + warp_n * 32 + (lane & 3) * 2;

    #pragma unroll
    for (int mt = 0; mt < 4; mt++) {
        #pragma unroll
        for (int half = 0; half < 2; half++) {
            const size_t row = (size_t)(er + mt * 16 + half * 8) * HH;
            #pragma unroll
            for (int nt = 0; nt < 4; nt++) {
                const int n = ec + nt * 8;
                const float* a2 = &acc[mt][nt][half * 2];
                if (!GATE) {
                    float2 v = { tanhf(a2[0] * INV_WSCALE), tanhf(a2[1] * INV_WSCALE) };
                    *(float2*)(&out0[row + n]) = v;
                } else {
                    float2 bi = *(const float2*)(&bias[n]);
                    float2 sv = *(const float2*)(&state[row + n]);
                    float2 vv = *(const float2*)(&values_in[row + n]);
                    float2 pg = { a2[0] * INV_WSCALE + bi.x, a2[1] * INV_WSCALE + bi.y };
                    float2 g  = { fminf(fmaxf(pg.x, 0.f), 1.f), fminf(fmaxf(pg.y, 0.f), 1.f) };
                    float2 ph = { sv.x * (1.f - g.x) + vv.x * g.x,
                                  sv.y * (1.f - g.y) + vv.y * g.y };
                    float2 nh = { fmaxf(ph.x, 0.f), fmaxf(ph.y, 0.f) };
                    *(float2*)(&out0[row + n])    = pg;
                    *(float2*)(&gate_o[row + n])  = g;
                    *(float2*)(&pre_h_o[row + n]) = ph;
                    *(float2*)(&new_h_o[row + n]) = nh;
                }
            }
        }
    }
}

// ---------------- launch ----------------
extern "C" void kernel_launch(void* const* d_in, const int* in_sizes, int n_in,
                              void* d_out, int out_size) {
    const float* input  = (const float*)d_in[0];
    const float* state  = (const float*)d_in[1];
    const float* gate_w = (const float*)d_in[2];
    const float* gate_b = (const float*)d_in[3];
    const float* w_i    = (const float*)d_in[4];

    float* out = (float*)d_out;
    float* new_h    = out;
    float* concat   = new_h + (size_t)Bb * HH;
    float* pre_gate = concat + (size_t)Bb * KG;
    float* gate     = pre_gate + (size_t)Bb * HH;
    float* values   = gate + (size_t)Bb * HH;
    float* pre_h    = values + (size_t)Bb * HH;

    void *cah, *wgh, *wih;
    cudaGetSymbolAddress(&cah, g_CAh);
    cudaGetSymbolAddress(&wgh, g_Wgh);
    cudaGetSymbolAddress(&wih, g_Wih);

    cudaFuncSetAttribute(gemm_mma<false>, cudaFuncAttributeMaxDynamicSharedMemorySize, SMEM_TOTAL);
    cudaFuncSetAttribute(gemm_mma<true>,  cudaFuncAttributeMaxDynamicSharedMemorySize, SMEM_TOTAL);

    convertA<<<(Bb * 512) / 256, 256>>>((const float4*)input, (const float4*)state,
                                        (float4*)concat);
    convertW<<<(HH * KG / 4) / 256, 256>>>((const float4*)gate_w, (__half*)wgh, HH * KG / 4);
    convertW<<<(HH * INN / 4) / 256, 256>>>((const float4*)w_i, (__half*)wih, HH * INN / 4);

    dim3 grid(HH / BN, Bb / BM);  // (16, 64)
    gemm_mma<false><<<grid, NTH, SMEM_TOTAL>>>(
        (const __half*)cah, (const __half*)wih, INN,
        nullptr, nullptr, nullptr, values, nullptr, nullptr, nullptr);

    gemm_mma<true><<<grid, NTH, SMEM_TOTAL>>>(
        (const __half*)cah, (const __half*)wgh, KG,
        state, gate_b, values, pre_gate, gate, pre_h, new_h);
}